// round 12
// baseline (speedup 1.0000x reference)
#include <cuda_runtime.h>
#include <cuda_bf16.h>
#include <stdint.h>
#include <cstdint>
#include <math.h>

#define BATCH 8
#define C_IN 256
#define C_INT 128
#define NSP 4096   // H*W = 64*64
#define MSP 1024   // pooled spatial = 32*32
#define NPIX 32768 // BATCH*NSP

// ---------------- scratch (static device arrays; no allocation) ----------------
__device__ float d_theta[BATCH * C_INT * NSP];                      // [B][Ci][N] fp32
__device__ __align__(16) __nv_bfloat16 d_phi_h[BATCH * MSP * C_INT];   // [B][M][Ci]
__device__ __align__(16) __nv_bfloat16 d_phi_l[BATCH * MSP * C_INT];
__device__ __align__(16) __nv_bfloat16 d_g_h[BATCH * C_INT * MSP];     // [B][Ci][M]
__device__ __align__(16) __nv_bfloat16 d_g_l[BATCH * C_INT * MSP];
__device__ __align__(16) __nv_bfloat16 d_y_h[BATCH * NSP * C_INT];     // [B][N][Ci]
__device__ __align__(16) __nv_bfloat16 d_y_l[BATCH * NSP * C_INT];
__device__ float d_Wy[BATCH * C_IN * NSP];                          // [B][C][N]
__device__ __align__(16) __nv_bfloat16 d_wp_h[384 * C_IN];             // packed conv weights
__device__ __align__(16) __nv_bfloat16 d_wp_l[384 * C_IN];
__device__ __align__(16) __nv_bfloat16 d_wW_h[C_IN * C_INT];           // W conv weights
__device__ __align__(16) __nv_bfloat16 d_wW_l[C_IN * C_INT];
__device__ float d_bpack[384];
__device__ float d_sum  [C_IN];
__device__ float d_sumsq[C_IN];

// ======================= warp-MMA helpers (sm_80+, safe on sm_103) =======================
__device__ __forceinline__ uint32_t smem_u32(const void* p) {
    uint32_t a;
    asm("{ .reg .u64 t; cvta.to.shared.u64 t, %1; cvt.u32.u64 %0, t; }" : "=r"(a) : "l"(p));
    return a;
}
__device__ __forceinline__ void ldsm4(uint32_t* r, uint32_t addr) {
    asm volatile("ldmatrix.sync.aligned.m8n8.x4.shared.b16 {%0,%1,%2,%3}, [%4];"
        : "=r"(r[0]), "=r"(r[1]), "=r"(r[2]), "=r"(r[3]) : "r"(addr));
}
__device__ __forceinline__ void mma_bf16(float* c, const uint32_t* a, uint32_t b0, uint32_t b1) {
    asm volatile("mma.sync.aligned.m16n8k16.row.col.f32.bf16.bf16.f32 "
        "{%0,%1,%2,%3}, {%4,%5,%6,%7}, {%8,%9}, {%0,%1,%2,%3};"
        : "+f"(c[0]), "+f"(c[1]), "+f"(c[2]), "+f"(c[3])
        : "r"(a[0]), "r"(a[1]), "r"(a[2]), "r"(a[3]), "r"(b0), "r"(b1));
}
__device__ __forceinline__ void split2(float v0, float v1, uint32_t& hi, uint32_t& lo) {
    __nv_bfloat16 h0 = __float2bfloat16(v0), h1 = __float2bfloat16(v1);
    float r0 = v0 - __bfloat162float(h0), r1 = v1 - __bfloat162float(h1);
    __nv_bfloat16 l0 = __float2bfloat16(r0), l1 = __float2bfloat16(r1);
    hi = (uint32_t)__bfloat16_as_ushort(h0) | ((uint32_t)__bfloat16_as_ushort(h1) << 16);
    lo = (uint32_t)__bfloat16_as_ushort(l0) | ((uint32_t)__bfloat16_as_ushort(l1) << 16);
}
__device__ __forceinline__ void cp16(uint32_t dst, const void* src) {
    asm volatile("cp.async.cg.shared.global [%0], [%1], 16;" :: "r"(dst), "l"(src));
}
#define CP_COMMIT() asm volatile("cp.async.commit_group;" ::: "memory")
#define CP_WAIT0()  asm volatile("cp.async.wait_group 0;" ::: "memory")
#define CP_WAIT1()  asm volatile("cp.async.wait_group 1;" ::: "memory")

// SMEM tile: 128 rows x 128 bf16, pitch 136 bf16 (272 B). Tile = 34816 B.
#define SPITCH 136
// attention smem: theta + dedicated phi + dedicated g buffers (double-buffered pipeline)
#define A_TH_HI 0
#define A_TH_LO 34816
#define A_PH 69632
#define A_PL 104448
#define A_GH 139264
#define A_GL 174080
#define ATTN_SMEM 208896
// wconv smem
#define TH_HI 0
#define TH_LO 34816
#define CH_HI 69632
#define CH_LO 104448
#define WCONV_SMEM 139264
// conv3 smem (A + two X chunks, all split)
#define C3_A_HI 0
#define C3_A_LO 34816
#define C3_X_HI(kc) (69632 + (kc) * 69632)
#define C3_X_LO(kc) (104448 + (kc) * 69632)
#define C3_SMEM 208896

// ---------------- pack theta/phi/g weights into split bf16 [384,256] ----------------
__global__ void pack_kernel(const float* __restrict__ tw, const float* __restrict__ tb,
                            const float* __restrict__ pw, const float* __restrict__ pb,
                            const float* __restrict__ gw, const float* __restrict__ gb) {
    int row = blockIdx.x;
    int t = threadIdx.x;
    const float* w; const float* bs; int r;
    if (row < 128)      { w = tw; bs = tb; r = row; }
    else if (row < 256) { w = pw; bs = pb; r = row - 128; }
    else                { w = gw; bs = gb; r = row - 256; }
    float v = w[r * 256 + t];
    __nv_bfloat16 h = __float2bfloat16(v);
    d_wp_h[row * 256 + t] = h;
    d_wp_l[row * 256 + t] = __float2bfloat16(v - __bfloat162float(h));
    if (t == 0) d_bpack[row] = bs[r];
}

// ---------------- split W conv weights [256,128] ----------------
__global__ void wsplit_kernel(const float* __restrict__ Ww) {
    int idx = blockIdx.x * 256 + threadIdx.x;   // 0..32767
    float v = Ww[idx];
    __nv_bfloat16 h = __float2bfloat16(v);
    d_wW_h[idx] = h;
    d_wW_l[idx] = __float2bfloat16(v - __bfloat162float(h));
}

// ---------------- conv3 on tensor cores; x staged ONCE per tile; pool fused ----------
// grid (32 n-tiles, 8 batch), 256 threads (8 warps).
__global__ __launch_bounds__(256, 1) void conv3_tc_kernel(const float* __restrict__ x) {
    extern __shared__ __align__(16) char smem[];
    uint32_t sb = smem_u32(smem);
    int tid  = threadIdx.x;
    int wid  = tid >> 5;
    int lane = tid & 31;
    int b  = blockIdx.y;
    int bx = blockIdx.x;
    int n0 = bx * 128;
    int wn0 = wid * 16;
    int g   = lane >> 2;
    int tig = lane & 3;
    int within = lane & 7, sub = lane >> 3;
    uint32_t a_loff = (uint32_t)((wn0 + (sub & 1) * 8 + within) * (SPITCH * 2) + (sub >> 1) * 16);
    uint32_t b_loff = (uint32_t)(((sub >> 1) * 8 + within) * (SPITCH * 2) + (sub & 1) * 16);

    const float* xb = x + (size_t)b * C_IN * NSP;

    // ---- stage BOTH x chunks: [k][n] -> smem [n][k] split hi/lo (transpose, once) ----
#pragma unroll
    for (int kc = 0; kc < 2; kc++) {
        int k0 = kc * 128;
        char* xh = smem + C3_X_HI(kc);
        char* xl = smem + C3_X_LO(kc);
        for (int it = 0; it < 32; it++) {
            int lin = tid + it * 256;
            int k   = lin >> 6;
            int n2  = (lin & 63) * 2;
            const float* src = xb + (size_t)(k0 + k) * NSP + n0 + n2;
            float v0 = src[0], v1 = src[1];
            __nv_bfloat16 h0 = __float2bfloat16(v0), h1 = __float2bfloat16(v1);
            float r0 = v0 - __bfloat162float(h0), r1 = v1 - __bfloat162float(h1);
            ((__nv_bfloat16*)xh)[n2 * SPITCH + k] = h0;
            ((__nv_bfloat16*)xh)[(n2 + 1) * SPITCH + k] = h1;
            ((__nv_bfloat16*)xl)[n2 * SPITCH + k] = __float2bfloat16(r0);
            ((__nv_bfloat16*)xl)[(n2 + 1) * SPITCH + k] = __float2bfloat16(r1);
        }
    }

    for (int by = 0; by < 3; by++) {
        float ya[16][4];
#pragma unroll
        for (int t = 0; t < 16; t++)
#pragma unroll
            for (int j = 0; j < 4; j++) ya[t][j] = 0.f;

        for (int kc = 0; kc < 2; kc++) {
            __syncthreads();   // protect A overwrite (and X visibility on first pass)
            // ---- stage A: copy pre-split wpack rows [by*128, +128), k-chunk kc ----
            {
                const uint4* srcH = (const uint4*)(d_wp_h + (size_t)(by * 128) * 256 + kc * 128);
                const uint4* srcL = (const uint4*)(d_wp_l + (size_t)(by * 128) * 256 + kc * 128);
#pragma unroll
                for (int it = 0; it < 8; it++) {
                    int lin = tid + it * 256;       // 0..2047
                    int row = lin >> 4, v = lin & 15;
                    // gmem row pitch = 256 bf16 = 32 uint4
                    *(uint4*)(smem + C3_A_HI + row * (SPITCH * 2) + v * 16) = srcH[row * 32 + v];
                    *(uint4*)(smem + C3_A_LO + row * (SPITCH * 2) + v * 16) = srcL[row * 32 + v];
                }
            }
            __syncthreads();

            uint32_t xh_base = sb + C3_X_HI(kc), xl_base = sb + C3_X_LO(kc);
#pragma unroll
            for (int k8 = 0; k8 < 8; k8++) {
                uint32_t ka = (uint32_t)(k8 * 32);
                uint32_t ah[4], al[4];
                ldsm4(ah, sb + C3_A_HI + a_loff + ka);
                ldsm4(al, sb + C3_A_LO + a_loff + ka);
#pragma unroll
                for (int t = 0; t < 8; t++) {
                    uint32_t bo = b_loff + (uint32_t)(t * 16 * SPITCH * 2) + ka;
                    uint32_t bh[4], bl[4];
                    ldsm4(bh, xh_base + bo);
                    ldsm4(bl, xl_base + bo);
                    mma_bf16(ya[2 * t],     ah, bh[0], bh[1]);
                    mma_bf16(ya[2 * t + 1], ah, bh[2], bh[3]);
                    mma_bf16(ya[2 * t],     ah, bl[0], bl[1]);
                    mma_bf16(ya[2 * t + 1], ah, bl[2], bl[3]);
                    mma_bf16(ya[2 * t],     al, bh[0], bh[1]);
                    mma_bf16(ya[2 * t + 1], al, bh[2], bh[3]);
                }
            }
        }

        // ---- epilogue ----
        int row0 = by * 128;
        float b0 = d_bpack[row0 + wn0 + g];
        float b1 = d_bpack[row0 + wn0 + g + 8];
#pragma unroll
        for (int t = 0; t < 16; t++) {
            ya[t][0] += b0; ya[t][1] += b0;
            ya[t][2] += b1; ya[t][3] += b1;
        }
        int ci0 = wn0 + g, ci1 = wn0 + g + 8;

        if (by == 0) {
            float* dst0 = d_theta + ((size_t)b * C_INT + ci0) * NSP + n0;
            float* dst1 = d_theta + ((size_t)b * C_INT + ci1) * NSP + n0;
#pragma unroll
            for (int t = 0; t < 16; t++) {
                int c = t * 8 + tig * 2;
                *(float2*)(dst0 + c) = make_float2(ya[t][0], ya[t][1]);
                *(float2*)(dst1 + c) = make_float2(ya[t][2], ya[t][3]);
            }
        } else {
            // 2x2 maxpool fully fragment-local, then split-store bf16 hi/lo
#pragma unroll
            for (int t = 0; t < 8; t++) {
                float p0 = fmaxf(fmaxf(ya[t][0], ya[t][1]), fmaxf(ya[t + 8][0], ya[t + 8][1]));
                float p1 = fmaxf(fmaxf(ya[t][2], ya[t][3]), fmaxf(ya[t + 8][2], ya[t + 8][3]));
                int m = bx * 32 + t * 4 + tig;
                __nv_bfloat16 h0 = __float2bfloat16(p0);
                __nv_bfloat16 l0 = __float2bfloat16(p0 - __bfloat162float(h0));
                __nv_bfloat16 h1 = __float2bfloat16(p1);
                __nv_bfloat16 l1 = __float2bfloat16(p1 - __bfloat162float(h1));
                if (by == 1) {
                    size_t base = ((size_t)b * MSP + m) * C_INT;
                    d_phi_h[base + ci0] = h0; d_phi_l[base + ci0] = l0;
                    d_phi_h[base + ci1] = h1; d_phi_l[base + ci1] = l1;
                } else {
                    size_t base0 = ((size_t)b * C_INT + ci0) * MSP + m;
                    size_t base1 = ((size_t)b * C_INT + ci1) * MSP + m;
                    d_g_h[base0] = h0; d_g_l[base0] = l0;
                    d_g_h[base1] = h1; d_g_l[base1] = l1;
                }
            }
        }
    }
}

// ---------------- attention via mma.sync bf16x3, cp.async double-buffered pipeline ----
// grid (32, 8), 256 threads (8 warps); block = 128 n-rows.
__global__ __launch_bounds__(256, 1) void attn_tc_kernel() {
    extern __shared__ __align__(16) char smem[];
    uint32_t sb = smem_u32(smem);
    int tid  = threadIdx.x;
    int wid  = tid >> 5;
    int lane = tid & 31;
    int b  = blockIdx.y;
    int n0 = blockIdx.x * 128;
    int wn0 = wid * 16;
    int g   = lane >> 2;
    int tig = lane & 3;
    int within = lane & 7, sub = lane >> 3;
    uint32_t a_loff = (uint32_t)((wn0 + (sub & 1) * 8 + within) * (SPITCH * 2) + (sub >> 1) * 16);
    uint32_t b_loff = (uint32_t)(((sub >> 1) * 8 + within) * (SPITCH * 2) + (sub & 1) * 16);

    int s_row = tid >> 4, s_v = tid & 15;     // staging coords: 256 thr -> 16 rows x 16 vec
    uint32_t s_off = (uint32_t)(s_row * (SPITCH * 2) + s_v * 16);

    // ---- kick off phi chunk 0 copy (overlaps theta scalar staging) ----
    {
        const __nv_bfloat16* ph = d_phi_h + ((size_t)b * MSP) * C_INT;
        const __nv_bfloat16* pl = d_phi_l + ((size_t)b * MSP) * C_INT;
#pragma unroll
        for (int it = 0; it < 8; it++) {
            uint32_t o = s_off + (uint32_t)(it * 16 * SPITCH * 2);
            const __nv_bfloat16* sh = ph + (size_t)(s_row + it * 16) * C_INT + s_v * 8;
            const __nv_bfloat16* sl = pl + (size_t)(s_row + it * 16) * C_INT + s_v * 8;
            cp16(sb + A_PH + o, sh);
            cp16(sb + A_PL + o, sl);
        }
        CP_COMMIT();
    }

    // ---- stage theta tile [n][k=ci] split hi/lo (transpose from fp32; once per block) ----
    {
        const float* tp = d_theta + (size_t)b * C_INT * NSP + n0;
        for (int it = 0; it < 32; it++) {
            int lin = tid + it * 256;
            int ci  = lin >> 6;
            int n2  = (lin & 63) * 2;
            float v0 = tp[(size_t)ci * NSP + n2];
            float v1 = tp[(size_t)ci * NSP + n2 + 1];
            __nv_bfloat16 h0 = __float2bfloat16(v0), h1 = __float2bfloat16(v1);
            float r0 = v0 - __bfloat162float(h0), r1 = v1 - __bfloat162float(h1);
            __nv_bfloat16* th = (__nv_bfloat16*)(smem + A_TH_HI);
            __nv_bfloat16* tl = (__nv_bfloat16*)(smem + A_TH_LO);
            th[n2 * SPITCH + ci] = h0;
            th[(n2 + 1) * SPITCH + ci] = h1;
            tl[n2 * SPITCH + ci] = __float2bfloat16(r0);
            tl[(n2 + 1) * SPITCH + ci] = __float2bfloat16(r1);
        }
    }

    float ya[16][4];
#pragma unroll
    for (int t = 0; t < 16; t++)
#pragma unroll
        for (int j = 0; j < 4; j++) ya[t][j] = 0.f;
    float s0 = 0.f, s1 = 0.f;

    for (int mc = 0; mc < 8; mc++) {
        int m0 = mc * 128;
        CP_WAIT0();
        __syncthreads();    // phi(mc) + theta visible; all warps done reading GB (prev iter)

        // ---- issue g(mc) copy -> GB (overlaps MMA1) ----
        {
#pragma unroll
            for (int it = 0; it < 8; it++) {
                int row = s_row + it * 16;
                uint32_t o = s_off + (uint32_t)(it * 16 * SPITCH * 2);
                const __nv_bfloat16* sh = d_g_h + ((size_t)b * C_INT + row) * MSP + m0 + s_v * 8;
                const __nv_bfloat16* sl = d_g_l + ((size_t)b * C_INT + row) * MSP + m0 + s_v * 8;
                cp16(sb + A_GH + o, sh);
                cp16(sb + A_GL + o, sl);
            }
            CP_COMMIT();
        }

        // ---- MMA1: f[16 x 128] = theta x phi^T (bf16x3) ----
        float fa[16][4];
#pragma unroll
        for (int t = 0; t < 16; t++)
#pragma unroll
            for (int j = 0; j < 4; j++) fa[t][j] = 0.f;
#pragma unroll
        for (int k8 = 0; k8 < 8; k8++) {
            uint32_t ka = (uint32_t)(k8 * 32);
            uint32_t ah[4], al[4];
            ldsm4(ah, sb + A_TH_HI + a_loff + ka);
            ldsm4(al, sb + A_TH_LO + a_loff + ka);
#pragma unroll
            for (int t = 0; t < 8; t++) {
                uint32_t bo = b_loff + (uint32_t)(t * 16 * SPITCH * 2) + ka;
                uint32_t bh[4], bl[4];
                ldsm4(bh, sb + A_PH + bo);
                ldsm4(bl, sb + A_PL + bo);
                mma_bf16(fa[2 * t],     ah, bh[0], bh[1]);
                mma_bf16(fa[2 * t + 1], ah, bh[2], bh[3]);
                mma_bf16(fa[2 * t],     ah, bl[0], bl[1]);
                mma_bf16(fa[2 * t + 1], ah, bl[2], bl[3]);
                mma_bf16(fa[2 * t],     al, bh[0], bh[1]);
                mma_bf16(fa[2 * t + 1], al, bh[2], bh[3]);
            }
        }

        // ---- P = exp(f) in registers; split packed; row-sum ----
        uint32_t pAh[16], pBh[16], pAl[16], pBl[16];
#pragma unroll
        for (int t = 0; t < 16; t++) {
            float e0 = __expf(fa[t][0]);
            float e1 = __expf(fa[t][1]);
            float e2 = __expf(fa[t][2]);
            float e3 = __expf(fa[t][3]);
            s0 += e0 + e1;
            s1 += e2 + e3;
            split2(e0, e1, pAh[t], pAl[t]);
            split2(e2, e3, pBh[t], pBl[t]);
        }
        __syncthreads();    // all warps done reading PB

        // ---- issue phi(mc+1) copy -> PB (overlaps MMA2) ----
        if (mc < 7) {
            const __nv_bfloat16* ph = d_phi_h + ((size_t)b * MSP + m0 + 128) * C_INT;
            const __nv_bfloat16* pl = d_phi_l + ((size_t)b * MSP + m0 + 128) * C_INT;
#pragma unroll
            for (int it = 0; it < 8; it++) {
                uint32_t o = s_off + (uint32_t)(it * 16 * SPITCH * 2);
                cp16(sb + A_PH + o, ph + (size_t)(s_row + it * 16) * C_INT + s_v * 8);
                cp16(sb + A_PL + o, pl + (size_t)(s_row + it * 16) * C_INT + s_v * 8);
            }
            CP_COMMIT();
            CP_WAIT1();     // g(mc) done; phi(mc+1) may still be in flight
        } else {
            CP_WAIT0();
        }
        __syncthreads();    // g visible to all

        // ---- MMA2: y[16 x 128] += P x g^T (A from registers) ----
#pragma unroll
        for (int k8 = 0; k8 < 8; k8++) {
            uint32_t ka = (uint32_t)(k8 * 32);
            uint32_t ah[4] = {pAh[2 * k8], pBh[2 * k8], pAh[2 * k8 + 1], pBh[2 * k8 + 1]};
            uint32_t al[4] = {pAl[2 * k8], pBl[2 * k8], pAl[2 * k8 + 1], pBl[2 * k8 + 1]};
#pragma unroll
            for (int t = 0; t < 8; t++) {
                uint32_t bo = b_loff + (uint32_t)(t * 16 * SPITCH * 2) + ka;
                uint32_t bh[4], bl[4];
                ldsm4(bh, sb + A_GH + bo);
                ldsm4(bl, sb + A_GL + bo);
                mma_bf16(ya[2 * t],     ah, bh[0], bh[1]);
                mma_bf16(ya[2 * t + 1], ah, bh[2], bh[3]);
                mma_bf16(ya[2 * t],     ah, bl[0], bl[1]);
                mma_bf16(ya[2 * t + 1], ah, bl[2], bl[3]);
                mma_bf16(ya[2 * t],     al, bh[0], bh[1]);
                mma_bf16(ya[2 * t + 1], al, bh[2], bh[3]);
            }
        }
        // next iteration's top barrier protects GB from early overwrite
    }

    // ---- normalize by row sums; write y SPLIT bf16 [n][ci] ----
    s0 += __shfl_xor_sync(0xffffffffu, s0, 1);
    s0 += __shfl_xor_sync(0xffffffffu, s0, 2);
    s1 += __shfl_xor_sync(0xffffffffu, s1, 1);
    s1 += __shfl_xor_sync(0xffffffffu, s1, 2);
    float inv0 = 1.f / s0, inv1 = 1.f / s1;
    {
        int nrow0 = n0 + wn0 + g;
        size_t base0 = ((size_t)b * NSP + nrow0) * C_INT;
        size_t base1 = ((size_t)b * NSP + nrow0 + 8) * C_INT;
#pragma unroll
        for (int t = 0; t < 16; t++) {
            int ci = t * 8 + tig * 2;
            uint32_t h0, l0, h1, l1;
            split2(ya[t][0] * inv0, ya[t][1] * inv0, h0, l0);
            split2(ya[t][2] * inv1, ya[t][3] * inv1, h1, l1);
            *(uint32_t*)(d_y_h + base0 + ci) = h0;
            *(uint32_t*)(d_y_l + base0 + ci) = l0;
            *(uint32_t*)(d_y_h + base1 + ci) = h1;
            *(uint32_t*)(d_y_l + base1 + ci) = l1;
        }
    }
}

// ---------------- zero BN stats ----------------
__global__ void zero_stats_kernel() {
    int t = threadIdx.x;
    if (t < 256) { d_sum[t] = 0.f; d_sumsq[t] = 0.f; }
}

// ---------------- W conv on tensor cores; pre-split operands; BN stats fused ------
// grid (32, 2, 8), 256 threads; warp = 16 c-rows, K=128 single chunk.
__global__ __launch_bounds__(256, 1) void wconv_tc_kernel(const float* __restrict__ Wb) {
    extern __shared__ __align__(16) char smem[];
    uint32_t sb = smem_u32(smem);
    int tid  = threadIdx.x;
    int wid  = tid >> 5;
    int lane = tid & 31;
    int b  = blockIdx.z;
    int c0 = blockIdx.y * 128;
    int n0 = blockIdx.x * 128;
    int wn0 = wid * 16;
    int g   = lane >> 2;
    int tig = lane & 3;
    int within = lane & 7, sub = lane >> 3;
    uint32_t a_loff = (uint32_t)((wn0 + (sub & 1) * 8 + within) * (SPITCH * 2) + (sub >> 1) * 16);
    uint32_t b_loff = (uint32_t)(((sub >> 1) * 8 + within) * (SPITCH * 2) + (sub & 1) * 16);

    // ---- stage A (Ww rows c0..+128) and B (y rows n0..+128): cp.async copies ----
    {
        const uint4* aH = (const uint4*)(d_wW_h + (size_t)c0 * C_INT);
        const uint4* aL = (const uint4*)(d_wW_l + (size_t)c0 * C_INT);
        const uint4* bH = (const uint4*)(d_y_h + ((size_t)b * NSP + n0) * C_INT);
        const uint4* bL = (const uint4*)(d_y_l + ((size_t)b * NSP + n0) * C_INT);
#pragma unroll
        for (int it = 0; it < 8; it++) {
            int lin = tid + it * 256;
            int row = lin >> 4, v = lin & 15;
            uint32_t so = (uint32_t)(row * (SPITCH * 2) + v * 16);
            cp16(sb + TH_HI + so, aH + row * 16 + v);
            cp16(sb + TH_LO + so, aL + row * 16 + v);
            cp16(sb + CH_HI + so, bH + row * 16 + v);
            cp16(sb + CH_LO + so, bL + row * 16 + v);
        }
        CP_COMMIT();
        CP_WAIT0();
    }
    __syncthreads();

    float ya[16][4];
#pragma unroll
    for (int t = 0; t < 16; t++)
#pragma unroll
        for (int j = 0; j < 4; j++) ya[t][j] = 0.f;

#pragma unroll
    for (int k8 = 0; k8 < 8; k8++) {
        uint32_t ka = (uint32_t)(k8 * 32);
        uint32_t ah[4], al[4];
        ldsm4(ah, sb + TH_HI + a_loff + ka);
        ldsm4(al, sb + TH_LO + a_loff + ka);
#pragma unroll
        for (int t = 0; t < 8; t++) {
            uint32_t bo = b_loff + (uint32_t)(t * 16 * SPITCH * 2) + ka;
            uint32_t bh[4], bl[4];
            ldsm4(bh, sb + CH_HI + bo);
            ldsm4(bl, sb + CH_LO + bo);
            mma_bf16(ya[2 * t],     ah, bh[0], bh[1]);
            mma_bf16(ya[2 * t + 1], ah, bh[2], bh[3]);
            mma_bf16(ya[2 * t],     ah, bl[0], bl[1]);
            mma_bf16(ya[2 * t + 1], ah, bl[2], bl[3]);
            mma_bf16(ya[2 * t],     al, bh[0], bh[1]);
            mma_bf16(ya[2 * t + 1], al, bh[2], bh[3]);
        }
    }

    // ---- epilogue: bias, write Wy, per-channel sum/sumsq ----
    int c0g = c0 + wn0 + g;
    float b0 = Wb[c0g], b1 = Wb[c0g + 8];
    float s0 = 0.f, q0 = 0.f, s1 = 0.f, q1 = 0.f;
    float* dst0 = d_Wy + ((size_t)b * C_IN + c0g) * NSP + n0;
    float* dst1 = d_Wy + ((size_t)b * C_IN + c0g + 8) * NSP + n0;
#pragma unroll
    for (int t = 0; t < 16; t++) {
        float v0 = ya[t][0] + b0, v1 = ya[t][1] + b0;
        float v2 = ya[t][2] + b1, v3 = ya[t][3] + b1;
        int c = t * 8 + tig * 2;
        *(float2*)(dst0 + c) = make_float2(v0, v1);
        *(float2*)(dst1 + c) = make_float2(v2, v3);
        s0 += v0 + v1; q0 += v0 * v0 + v1 * v1;
        s1 += v2 + v3; q1 += v2 * v2 + v3 * v3;
    }
    s0 += __shfl_xor_sync(0xffffffffu, s0, 1);
    s0 += __shfl_xor_sync(0xffffffffu, s0, 2);
    q0 += __shfl_xor_sync(0xffffffffu, q0, 1);
    q0 += __shfl_xor_sync(0xffffffffu, q0, 2);
    s1 += __shfl_xor_sync(0xffffffffu, s1, 1);
    s1 += __shfl_xor_sync(0xffffffffu, s1, 2);
    q1 += __shfl_xor_sync(0xffffffffu, q1, 1);
    q1 += __shfl_xor_sync(0xffffffffu, q1, 2);
    if (tig == 0) {
        atomicAdd(&d_sum[c0g], s0);
        atomicAdd(&d_sumsq[c0g], q0);
        atomicAdd(&d_sum[c0g + 8], s1);
        atomicAdd(&d_sumsq[c0g + 8], q1);
    }
}

// ---------------- BN (training stats) + residual ----------------
__global__ __launch_bounds__(256) void finalize_kernel(const float* __restrict__ x,
                                                       const float* __restrict__ gamma,
                                                       const float* __restrict__ beta,
                                                       float* __restrict__ out) {
    size_t i4  = (size_t)blockIdx.x * 256 + threadIdx.x;
    size_t idx = i4 * 4;
    int c = (int)((idx >> 12) & 255);
    float mean = d_sum[c] * (1.f / (float)NPIX);
    float var  = d_sumsq[c] * (1.f / (float)NPIX) - mean * mean;
    float inv  = 1.f / sqrtf(fmaxf(var, 0.f) + 1e-5f);
    float ga = gamma[c] * inv;
    float be = beta[c] - mean * ga;
    float4 w  = *(const float4*)&d_Wy[idx];
    float4 xv = *(const float4*)&x[idx];
    float4 o;
    o.x = w.x * ga + be + xv.x;
    o.y = w.y * ga + be + xv.y;
    o.z = w.z * ga + be + xv.z;
    o.w = w.w * ga + be + xv.w;
    *(float4*)&out[idx] = o;
}

// ---------------- launcher ----------------
extern "C" void kernel_launch(void* const* d_in, const int* in_sizes, int n_in,
                              void* d_out, int out_size) {
    const float* x       = (const float*)d_in[0];
    const float* theta_w = (const float*)d_in[1];
    const float* theta_b = (const float*)d_in[2];
    const float* phi_w   = (const float*)d_in[3];
    const float* phi_b   = (const float*)d_in[4];
    const float* g_w     = (const float*)d_in[5];
    const float* g_b     = (const float*)d_in[6];
    const float* W_w     = (const float*)d_in[7];
    const float* W_b     = (const float*)d_in[8];
    const float* bn_g    = (const float*)d_in[9];
    const float* bn_b    = (const float*)d_in[10];
    float* out = (float*)d_out;

    cudaFuncSetAttribute(attn_tc_kernel, cudaFuncAttributeMaxDynamicSharedMemorySize, ATTN_SMEM);
    cudaFuncSetAttribute(conv3_tc_kernel, cudaFuncAttributeMaxDynamicSharedMemorySize, C3_SMEM);
    cudaFuncSetAttribute(wconv_tc_kernel, cudaFuncAttributeMaxDynamicSharedMemorySize, WCONV_SMEM);

    pack_kernel<<<384, 256>>>(theta_w, theta_b, phi_w, phi_b, g_w, g_b);
    wsplit_kernel<<<128, 256>>>(W_w);
    conv3_tc_kernel<<<dim3(32, BATCH), 256, C3_SMEM>>>(x);
    attn_tc_kernel<<<dim3(32, BATCH), 256, ATTN_SMEM>>>();
    zero_stats_kernel<<<1, 256>>>();
    wconv_tc_kernel<<<dim3(32, 2, BATCH), 256, WCONV_SMEM>>>(W_b);
    finalize_kernel<<<8192, 256>>>(x, bn_g, bn_b, out);
}